// round 10
// baseline (speedup 1.0000x reference)
#include <cuda_runtime.h>

// Dense CRF pairwise loss, B=1, C=2, H=W=96.
// Centered features (translation-invariant distances):
//   K_ij = 2^(-CY*dy^2) * C_i * 2^(g'_i.g'_j + nh_j),  C_i = 2^{nh_i}, nh = -|g'4|^2/2
// g'4 = centered (gx,gr,gg,gb); C_i folded into final per-i weights.
// Tile-symmetry: sum over a<=b tile pairs, off-diag doubled.
// Per-i weight hoisted: Sum_j k*(A_i+B_i*p_j) = A_i*Sum k + B_i*Sum k*p_j.
// TPB=384 (12 warps = 3/SMSP balanced), IPT=3 (1.0 LDS.128 per body).

#define Wdim   96
#define NPIX   9216
#define RPT    12            // rows per tile
#define ITILE  1152          // RPT*Wdim
#define NTILES 8
#define NTPAIR 36            // triangle incl diagonal
#define RPC    3             // j-rows per chunk
#define NCHUNK 4             // chunks per j-tile
#define NBLK   (NTPAIR*NCHUNK)  // 144 blocks = 1 wave
#define TPB    384
#define IPT    3
#define JP_ROW 48            // j-pairs per row
#define JP_CHUNK (RPC*JP_ROW)   // 144

__device__ float g_part[NBLK];
__device__ int   g_cnt = 0;

typedef unsigned long long u64;

__device__ __forceinline__ u64 splat2(float v) {
    u64 r; asm("mov.b64 %0,{%1,%1};" : "=l"(r) : "f"(v)); return r;
}
__device__ __forceinline__ u64 pk2(float a, float b) {
    u64 r; asm("mov.b64 %0,{%1,%2};" : "=l"(r) : "f"(a), "f"(b)); return r;
}
__device__ __forceinline__ void up2(u64 v, float& a, float& b) {
    asm("mov.b64 {%0,%1},%2;" : "=f"(a), "=f"(b) : "l"(v));
}
__device__ __forceinline__ u64 fma2(u64 a, u64 b, u64 c) {
    u64 d; asm("fma.rn.f32x2 %0,%1,%2,%3;" : "=l"(d) : "l"(a), "l"(b), "l"(c)); return d;
}
__device__ __forceinline__ u64 add2(u64 a, u64 b) {
    u64 d; asm("add.rn.f32x2 %0,%1,%2;" : "=l"(d) : "l"(a), "l"(b)); return d;
}
__device__ __forceinline__ float ex2f(float x) {
    float r; asm("ex2.approx.ftz.f32 %0,%1;" : "=f"(r) : "f"(x)); return r;
}

// centered 4-dim feature: gx,gr,gg,gb; nh = -|g'|^2/2; p class-0 prob
__device__ __forceinline__ void pix_feat4(const float* __restrict__ probs,
                                          const float* __restrict__ image, int n,
                                          float& gx, float& gr, float& gg,
                                          float& gb, float& nh, float& p) {
    const float SXY  = 0.080074306f;   // sqrt(log2e/225)
    const float SRGB = 9.6083684f;     // sqrt(64*log2e)
    const float CXO  = 47.5f;          // x center
    const float CRGB = 0.5f;           // rgb center
    gx = ((float)(n % Wdim) - CXO) * SXY;
    gr = (image[n]            - CRGB) * SRGB;
    gg = (image[NPIX + n]     - CRGB) * SRGB;
    gb = (image[2 * NPIX + n] - CRGB) * SRGB;
    nh = -0.5f * (gx*gx + gr*gr + gg*gg + gb*gb);
    p  = probs[n];
}

__global__ void __launch_bounds__(TPB) crf_fused(const float* __restrict__ probs,
                                                 const float* __restrict__ image,
                                                 float* __restrict__ out) {
    // j-features packed as f32x2 pairs: LDS.128 reg pairs feed fma.f32x2 directly
    __shared__ ulonglong2 sD[JP_CHUNK];   // {gx01, gr01}
    __shared__ ulonglong2 sE[JP_CHUNK];   // {gg01, gb01}
    __shared__ ulonglong2 sF[JP_CHUNK];   // {nh01, p01}
    __shared__ float      ws[TPB / 32];
    __shared__ bool       isLast;

    const int tid = threadIdx.x;
    const int bid = blockIdx.x;
    const int pairIdx = bid / NCHUNK;
    const int chunk   = bid % NCHUNK;

    int a = 0, b = 0, idx = pairIdx;
    #pragma unroll
    for (int aa = 0; aa < NTILES; ++aa) {
        int cnt = NTILES - aa;
        if (idx < cnt) { a = aa; b = aa + idx; break; }
        idx -= cnt;
    }

    const int jrow0 = b * RPT + chunk * RPC;     // first j image-row of this chunk
    const int jbase = jrow0 * Wdim;

    if (tid < JP_CHUNK) {
        int j0 = jbase + 2 * tid;
        float gx0, gr0, gg0, gb0, nh0, p0;
        float gx1, gr1, gg1, gb1, nh1, p1;
        pix_feat4(probs, image, j0,     gx0, gr0, gg0, gb0, nh0, p0);
        pix_feat4(probs, image, j0 + 1, gx1, gr1, gg1, gb1, nh1, p1);
        sD[tid] = make_ulonglong2(pk2(gx0, gx1), pk2(gr0, gr1));
        sE[tid] = make_ulonglong2(pk2(gg0, gg1), pk2(gb0, gb1));
        sF[tid] = make_ulonglong2(pk2(nh0, nh1), pk2(p0, p1));
    }

    const float wscale = (a == b) ? 1.0f : 2.0f;
    u64 gxi[IPT], gri[IPT], ggi[IPT], gbi[IPT];
    u64 accA[IPT], accB[IPT];          // Sum rowfac*Sum_row k ; same for k*pj
    float Ai[IPT], Bi[IPT], yi[IPT];
    #pragma unroll
    for (int m = 0; m < IPT; ++m) {
        int i = a * ITILE + tid + m * TPB;
        float gx, gr, gg, gb, nh, p;
        pix_feat4(probs, image, i, gx, gr, gg, gb, nh, p);
        gxi[m] = splat2(gx);
        gri[m] = splat2(gr); ggi[m] = splat2(gg); gbi[m] = splat2(gb);
        yi[m]  = (float)(i / Wdim);
        float Ci = ex2f(nh) * wscale;      // 2^{nh_i} folded into weights
        Ai[m] = Ci * p;
        Bi[m] = Ci * (1.0f - 2.0f * p);
        accA[m] = 0ull; accB[m] = 0ull;
    }
    __syncthreads();

    const float CY = 0.0032059890f;    // log2e / (2*15^2)
    #pragma unroll
    for (int r = 0; r < RPC; ++r) {
        // per-row y factor: 2^(-CY*(y_i - y_j)^2), y_j constant over the row
        u64 rowfac[IPT];
        u64 rA[IPT], rB[IPT];
        const float yj = (float)(jrow0 + r);
        #pragma unroll
        for (int m = 0; m < IPT; ++m) {
            float dy = yi[m] - yj;
            rowfac[m] = splat2(ex2f(-CY * dy * dy));
            rA[m] = 0ull; rB[m] = 0ull;
        }
        const int jpEnd = (r + 1) * JP_ROW;
        #pragma unroll 4
        for (int jp = r * JP_ROW; jp < jpEnd; ++jp) {
            ulonglong2 D = sD[jp], E = sE[jp], F = sF[jp];
            #pragma unroll
            for (int m = 0; m < IPT; ++m) {
                u64 t = fma2(gxi[m], D.x, F.x);   // c = nh_j from LDS
                t = fma2(gri[m], D.y, t);
                t = fma2(ggi[m], E.x, t);
                t = fma2(gbi[m], E.y, t);
                float t0, t1; up2(t, t0, t1);
                u64 k = pk2(ex2f(t0), ex2f(t1));
                rA[m] = add2(rA[m], k);
                rB[m] = fma2(k, F.y, rB[m]);
            }
        }
        #pragma unroll
        for (int m = 0; m < IPT; ++m) {
            accA[m] = fma2(rowfac[m], rA[m], accA[m]);
            accB[m] = fma2(rowfac[m], rB[m], accB[m]);
        }
    }

    // apply per-i weights, block reduce (fixed order -> deterministic)
    float s = 0.0f;
    #pragma unroll
    for (int m = 0; m < IPT; ++m) {
        float a0, a1, b0, b1;
        up2(accA[m], a0, a1);
        up2(accB[m], b0, b1);
        s += Ai[m] * (a0 + a1) + Bi[m] * (b0 + b1);
    }
    #pragma unroll
    for (int off = 16; off > 0; off >>= 1)
        s += __shfl_down_sync(0xffffffffu, s, off);
    if ((tid & 31) == 0) ws[tid >> 5] = s;
    __syncthreads();
    if (tid == 0) {
        float t = 0.0f;
        #pragma unroll
        for (int k = 0; k < TPB / 32; ++k) t += ws[k];
        g_part[bid] = t;
        __threadfence();
        int old = atomicAdd(&g_cnt, 1);
        isLast = (old == NBLK - 1);
    }
    __syncthreads();
    if (isLast && tid < 32) {
        __threadfence();
        float acc2 = 0.0f;
        #pragma unroll
        for (int k = tid; k < NBLK; k += 32) acc2 += __ldcg(&g_part[k]);
        #pragma unroll
        for (int off = 16; off > 0; off >>= 1)
            acc2 += __shfl_down_sync(0xffffffffu, acc2, off);
        if (tid == 0) {
            out[0] = acc2 * (1.0f / (float)NPIX);
            g_cnt = 0;   // reset for next graph replay
        }
    }
}

extern "C" void kernel_launch(void* const* d_in, const int* in_sizes, int n_in,
                              void* d_out, int out_size) {
    const float* probs = (const float*)d_in[0];
    const float* image = (const float*)d_in[1];
    float* out = (float*)d_out;
    crf_fused<<<NBLK, TPB>>>(probs, image, out);
}

// round 11
// speedup vs baseline: 1.0102x; 1.0102x over previous
#include <cuda_runtime.h>

// Dense CRF pairwise loss, B=1, C=2, H=W=96.
// Centered features (translation-invariant distances):
//   K_ij = 2^(-CY*dy^2) * C_i * 2^(g'_i.g'_j + nh_j),  C_i = 2^{nh_i}, nh = -|g'4|^2/2
// g'4 = centered (gx,gr,gg,gb); C_i folded into final per-i weights.
// Tile-symmetry: sum over a<=b tile pairs, off-diag doubled.
// Per-i weight hoisted: Sum_j k*(A_i+B_i*p_j) = A_i*Sum k + B_i*Sum k*p_j.
// TPB=384 (3 warps/SMSP balanced), IPT=3, 2 blocks/SM -> 6 warps/SMSP.
// Chunks of 72 jp (1.5 rows) processed as row segments for the y-factor.

#define Wdim   96
#define NPIX   9216
#define RPT    12            // rows per tile
#define ITILE  1152          // RPT*Wdim
#define NTILES 8
#define NTPAIR 36            // triangle incl diagonal
#define NCHUNK 8             // chunks per j-tile (72 jp each)
#define NBLK   (NTPAIR*NCHUNK)  // 288 blocks = 2 per SM
#define TPB    384
#define IPT    3
#define JP_ROW 48            // j-pairs per row
#define JP_TILE 576          // jp per tile
#define JP_CHUNK 72          // jp per chunk (1.5 rows)

__device__ float g_part[NBLK];
__device__ int   g_cnt = 0;

typedef unsigned long long u64;

__device__ __forceinline__ u64 splat2(float v) {
    u64 r; asm("mov.b64 %0,{%1,%1};" : "=l"(r) : "f"(v)); return r;
}
__device__ __forceinline__ u64 pk2(float a, float b) {
    u64 r; asm("mov.b64 %0,{%1,%2};" : "=l"(r) : "f"(a), "f"(b)); return r;
}
__device__ __forceinline__ void up2(u64 v, float& a, float& b) {
    asm("mov.b64 {%0,%1},%2;" : "=f"(a), "=f"(b) : "l"(v));
}
__device__ __forceinline__ u64 fma2(u64 a, u64 b, u64 c) {
    u64 d; asm("fma.rn.f32x2 %0,%1,%2,%3;" : "=l"(d) : "l"(a), "l"(b), "l"(c)); return d;
}
__device__ __forceinline__ u64 add2(u64 a, u64 b) {
    u64 d; asm("add.rn.f32x2 %0,%1,%2;" : "=l"(d) : "l"(a), "l"(b)); return d;
}
__device__ __forceinline__ float ex2f(float x) {
    float r; asm("ex2.approx.ftz.f32 %0,%1;" : "=f"(r) : "f"(x)); return r;
}

// centered 4-dim feature: gx,gr,gg,gb; nh = -|g'|^2/2; p class-0 prob
__device__ __forceinline__ void pix_feat4(const float* __restrict__ probs,
                                          const float* __restrict__ image, int n,
                                          float& gx, float& gr, float& gg,
                                          float& gb, float& nh, float& p) {
    const float SXY  = 0.080074306f;   // sqrt(log2e/225)
    const float SRGB = 9.6083684f;     // sqrt(64*log2e)
    const float CXO  = 47.5f;          // x center
    const float CRGB = 0.5f;           // rgb center
    gx = ((float)(n % Wdim) - CXO) * SXY;
    gr = (image[n]            - CRGB) * SRGB;
    gg = (image[NPIX + n]     - CRGB) * SRGB;
    gb = (image[2 * NPIX + n] - CRGB) * SRGB;
    nh = -0.5f * (gx*gx + gr*gr + gg*gg + gb*gb);
    p  = probs[n];
}

__global__ void __launch_bounds__(TPB) crf_fused(const float* __restrict__ probs,
                                                 const float* __restrict__ image,
                                                 float* __restrict__ out) {
    // j-features packed as f32x2 pairs: LDS.128 reg pairs feed fma.f32x2 directly
    __shared__ ulonglong2 sD[JP_CHUNK];   // {gx01, gr01}
    __shared__ ulonglong2 sE[JP_CHUNK];   // {gg01, gb01}
    __shared__ ulonglong2 sF[JP_CHUNK];   // {nh01, p01}
    __shared__ float      ws[TPB / 32];
    __shared__ bool       isLast;

    const int tid = threadIdx.x;
    const int bid = blockIdx.x;
    const int pairIdx = bid / NCHUNK;
    const int chunk   = bid % NCHUNK;

    int a = 0, b = 0, idx = pairIdx;
    #pragma unroll
    for (int aa = 0; aa < NTILES; ++aa) {
        int cnt = NTILES - aa;
        if (idx < cnt) { a = aa; b = aa + idx; break; }
        idx -= cnt;
    }

    const int jp0 = chunk * JP_CHUNK;            // tile-local first jp
    const int jbase = b * ITILE + 2 * jp0;       // global pixel index of first j

    if (tid < JP_CHUNK) {
        int j0 = jbase + 2 * tid;
        float gx0, gr0, gg0, gb0, nh0, p0;
        float gx1, gr1, gg1, gb1, nh1, p1;
        pix_feat4(probs, image, j0,     gx0, gr0, gg0, gb0, nh0, p0);
        pix_feat4(probs, image, j0 + 1, gx1, gr1, gg1, gb1, nh1, p1);
        sD[tid] = make_ulonglong2(pk2(gx0, gx1), pk2(gr0, gr1));
        sE[tid] = make_ulonglong2(pk2(gg0, gg1), pk2(gb0, gb1));
        sF[tid] = make_ulonglong2(pk2(nh0, nh1), pk2(p0, p1));
    }

    const float wscale = (a == b) ? 1.0f : 2.0f;
    u64 gxi[IPT], gri[IPT], ggi[IPT], gbi[IPT];
    u64 accA[IPT], accB[IPT];          // Sum rowfac*Sum_row k ; same for k*pj
    float Ai[IPT], Bi[IPT], yi[IPT];
    #pragma unroll
    for (int m = 0; m < IPT; ++m) {
        int i = a * ITILE + tid + m * TPB;
        float gx, gr, gg, gb, nh, p;
        pix_feat4(probs, image, i, gx, gr, gg, gb, nh, p);
        gxi[m] = splat2(gx);
        gri[m] = splat2(gr); ggi[m] = splat2(gg); gbi[m] = splat2(gb);
        yi[m]  = (float)(i / Wdim);
        float Ci = ex2f(nh) * wscale;      // 2^{nh_i} folded into weights
        Ai[m] = Ci * p;
        Bi[m] = Ci * (1.0f - 2.0f * p);
        accA[m] = 0ull; accB[m] = 0ull;
    }
    __syncthreads();

    const float CY = 0.0032059890f;    // log2e / (2*15^2)
    const int jrowTile = b * RPT;      // first image row of j-tile
    // chunk = 1.5 rows -> at most 2 row segments
    int jp = jp0;                      // tile-local jp cursor
    const int jpEndChunk = jp0 + JP_CHUNK;
    #pragma unroll
    for (int seg = 0; seg < 2; ++seg) {
        const int row = jp / JP_ROW;                       // tile-local row
        const int segEnd = min(jpEndChunk, (row + 1) * JP_ROW);
        // per-row y factor: 2^(-CY*(y_i - y_j)^2)
        u64 rowfac[IPT];
        u64 rA[IPT], rB[IPT];
        const float yj = (float)(jrowTile + row);
        #pragma unroll
        for (int m = 0; m < IPT; ++m) {
            float dy = yi[m] - yj;
            rowfac[m] = splat2(ex2f(-CY * dy * dy));
            rA[m] = 0ull; rB[m] = 0ull;
        }
        #pragma unroll 4
        for (; jp < segEnd; ++jp) {
            const int js = jp - jp0;                       // smem index
            ulonglong2 D = sD[js], E = sE[js], F = sF[js];
            #pragma unroll
            for (int m = 0; m < IPT; ++m) {
                u64 t = fma2(gxi[m], D.x, F.x);   // c = nh_j from LDS
                t = fma2(gri[m], D.y, t);
                t = fma2(ggi[m], E.x, t);
                t = fma2(gbi[m], E.y, t);
                float t0, t1; up2(t, t0, t1);
                u64 k = pk2(ex2f(t0), ex2f(t1));
                rA[m] = add2(rA[m], k);
                rB[m] = fma2(k, F.y, rB[m]);
            }
        }
        #pragma unroll
        for (int m = 0; m < IPT; ++m) {
            accA[m] = fma2(rowfac[m], rA[m], accA[m]);
            accB[m] = fma2(rowfac[m], rB[m], accB[m]);
        }
        if (jp >= jpEndChunk) break;
    }

    // apply per-i weights, block reduce (fixed order -> deterministic)
    float s = 0.0f;
    #pragma unroll
    for (int m = 0; m < IPT; ++m) {
        float a0, a1, b0, b1;
        up2(accA[m], a0, a1);
        up2(accB[m], b0, b1);
        s += Ai[m] * (a0 + a1) + Bi[m] * (b0 + b1);
    }
    #pragma unroll
    for (int off = 16; off > 0; off >>= 1)
        s += __shfl_down_sync(0xffffffffu, s, off);
    if ((tid & 31) == 0) ws[tid >> 5] = s;
    __syncthreads();
    if (tid == 0) {
        float t = 0.0f;
        #pragma unroll
        for (int k = 0; k < TPB / 32; ++k) t += ws[k];
        g_part[bid] = t;
        __threadfence();
        int old = atomicAdd(&g_cnt, 1);
        isLast = (old == NBLK - 1);
    }
    __syncthreads();
    if (isLast && tid < 32) {
        __threadfence();
        float acc2 = 0.0f;
        #pragma unroll
        for (int k = tid; k < NBLK; k += 32) acc2 += __ldcg(&g_part[k]);
        #pragma unroll
        for (int off = 16; off > 0; off >>= 1)
            acc2 += __shfl_down_sync(0xffffffffu, acc2, off);
        if (tid == 0) {
            out[0] = acc2 * (1.0f / (float)NPIX);
            g_cnt = 0;   // reset for next graph replay
        }
    }
}

extern "C" void kernel_launch(void* const* d_in, const int* in_sizes, int n_in,
                              void* d_out, int out_size) {
    const float* probs = (const float*)d_in[0];
    const float* image = (const float*)d_in[1];
    float* out = (float*)d_out;
    crf_fused<<<NBLK, TPB>>>(probs, image, out);
}